// round 8
// baseline (speedup 1.0000x reference)
#include <cuda_runtime.h>
#include <math.h>
#include <stdint.h>

#define Bsz 32
#define Ssz 2048
#define Isz 256
#define Hsz 256
#define Msz 1024   // 4*H, packed as m = j*4 + g  (g: 0=f,1=i,2=c,3=o)

typedef unsigned long long ull;

// ------------------------------- f32x2 helpers ---------------------------------
__device__ __forceinline__ ull pack2(float lo, float hi) {
    ull r; asm("mov.b64 %0, {%1,%2};" : "=l"(r) : "f"(lo), "f"(hi)); return r;
}
__device__ __forceinline__ void unpack2(float& lo, float& hi, ull v) {
    asm("mov.b64 {%0,%1}, %2;" : "=f"(lo), "=f"(hi) : "l"(v));
}
__device__ __forceinline__ void fma2(ull& d, ull a, ull b) {
    asm("fma.rn.f32x2 %0, %1, %2, %0;" : "+l"(d) : "l"(a), "l"(b));
}
__device__ __forceinline__ ull add2(ull a, ull b) {
    ull r; asm("add.rn.f32x2 %0, %1, %2;" : "=l"(r) : "l"(a), "l"(b)); return r;
}

// ------------------------------- mbarrier helpers ------------------------------
__device__ __forceinline__ void mbar_init(unsigned addr, unsigned count) {
    asm volatile("mbarrier.init.shared.b64 [%0], %1;" :: "r"(addr), "r"(count) : "memory");
}
__device__ __forceinline__ void mbar_expect_tx(unsigned addr, unsigned bytes) {
    asm volatile("mbarrier.arrive.expect_tx.shared.b64 _, [%0], %1;"
                 :: "r"(addr), "r"(bytes) : "memory");
}
__device__ __forceinline__ void mbar_wait(unsigned addr, unsigned parity) {
    unsigned done;
    asm volatile(
        "{\n\t.reg .pred p;\n\t"
        "mbarrier.try_wait.parity.acquire.cta.shared::cta.b64 p, [%1], %2;\n\t"
        "selp.b32 %0, 1, 0, p;\n\t}"
        : "=r"(done) : "r"(addr), "r"(parity) : "memory");
    if (!done) {
        asm volatile(
            "{\n\t.reg .pred P1;\n\t"
            "WL_%=:\n\t"
            "mbarrier.try_wait.parity.acquire.cta.shared::cta.b64 P1, [%0], %1, 0x989680;\n\t"
            "@P1 bra.uni WD_%=;\n\t"
            "bra.uni WL_%=;\n\t"
            "WD_%=:\n\t}"
            :: "r"(addr), "r"(parity) : "memory");
    }
}

// ------------------------------- device scratch -------------------------------
__device__ float g_Wx[Isz * Msz];                      // [k][m], x-part rows of W
__device__ float g_Wh[Hsz * Msz];                      // [k][m], h-part rows of W
__device__ float g_bias[Msz];
__device__ float g_xp[(size_t)Bsz * Ssz * Msz];        // [t][b][m]  (256 MB)

// ------------------------------- pack ------------------------------------------
__global__ void pack_kernel(const float* __restrict__ Wf, const float* __restrict__ Wi,
                            const float* __restrict__ Wc, const float* __restrict__ Wo,
                            const float* __restrict__ bf, const float* __restrict__ bi,
                            const float* __restrict__ bc, const float* __restrict__ bo) {
    int idx = blockIdx.x * blockDim.x + threadIdx.x;   // over (k in 0..511, j in 0..255)
    if (idx < 512 * 256) {
        int k = idx >> 8;      // row of W_all (0..511): [0,256) = h-part, [256,512) = x-part
        int j = idx & 255;
        const float* W[4] = {Wf, Wi, Wc, Wo};
        #pragma unroll
        for (int g = 0; g < 4; g++) {
            float v = W[g][k * Hsz + j];
            int m = j * 4 + g;
            if (k < Hsz) g_Wh[k * Msz + m] = v;
            else         g_Wx[(k - Hsz) * Msz + m] = v;
        }
        if (k == 0) {
            const float* bias[4] = {bf, bi, bc, bo};
            #pragma unroll
            for (int g = 0; g < 4; g++) g_bias[j * 4 + g] = bias[g][j];
        }
    }
}

// ------------------------------- xproj GEMM (f32x2) ----------------------------
#define XBM 128
#define XBN 128
#define XBK 8

__global__ __launch_bounds__(256) void xproj_kernel(const float* __restrict__ x) {
    __shared__ float As[XBK][XBM + 4];
    __shared__ float Bs[XBK][XBN];

    int bn = blockIdx.x;               // 0..7    (m blocks)
    int bm = blockIdx.y;               // 0..511  (row blocks)
    int tid = threadIdx.x;
    int tx = tid & 15;
    int ty = tid >> 4;

    int r0 = bm * XBM;
    int m0 = bn * XBN;

    int arow = tid >> 1, akq = tid & 1;
    int r = r0 + arow;
    int b = r & 31, t = r >> 5;
    const float* arow_ptr = x + ((size_t)b * Ssz + t) * Isz;

    int bk = tid >> 5, bmq = tid & 31;
    const float* brow_ptr = g_Wx + (size_t)bk * Msz + m0 + bmq * 4;

    ull acc2[8][4];
    #pragma unroll
    for (int i = 0; i < 8; i++)
        #pragma unroll
        for (int jp = 0; jp < 4; jp++) acc2[i][jp] = 0ull;

    for (int k0 = 0; k0 < Isz; k0 += XBK) {
        float4 av = *(const float4*)(arow_ptr + k0 + akq * 4);
        As[akq * 4 + 0][arow] = av.x;
        As[akq * 4 + 1][arow] = av.y;
        As[akq * 4 + 2][arow] = av.z;
        As[akq * 4 + 3][arow] = av.w;
        *(float4*)&Bs[bk][bmq * 4] = *(const float4*)(brow_ptr + (size_t)k0 * Msz);
        __syncthreads();
        #pragma unroll
        for (int kk = 0; kk < XBK; kk++) {
            float4 aA = *(float4*)&As[kk][ty * 8];
            float4 aB = *(float4*)&As[kk][ty * 8 + 4];
            ulonglong2 bL = *(ulonglong2*)&Bs[kk][tx * 8];
            ulonglong2 bH = *(ulonglong2*)&Bs[kk][tx * 8 + 4];
            ull b2[4] = {bL.x, bL.y, bH.x, bH.y};
            float ar[8] = {aA.x, aA.y, aA.z, aA.w, aB.x, aB.y, aB.z, aB.w};
            #pragma unroll
            for (int i = 0; i < 8; i++) {
                ull a2 = pack2(ar[i], ar[i]);
                #pragma unroll
                for (int jp = 0; jp < 4; jp++) fma2(acc2[i][jp], a2, b2[jp]);
            }
        }
        __syncthreads();
    }

    ull bias2[4];
    {
        ulonglong2 bL = *(const ulonglong2*)(g_bias + m0 + tx * 8);
        ulonglong2 bH = *(const ulonglong2*)(g_bias + m0 + tx * 8 + 4);
        bias2[0] = bL.x; bias2[1] = bL.y; bias2[2] = bH.x; bias2[3] = bH.y;
    }
    #pragma unroll
    for (int i = 0; i < 8; i++) {
        int rr = r0 + ty * 8 + i;
        float* dst = g_xp + (size_t)rr * Msz + m0 + tx * 8;
        ulonglong2 oL, oH;
        oL.x = add2(acc2[i][0], bias2[0]);
        oL.y = add2(acc2[i][1], bias2[1]);
        oH.x = add2(acc2[i][2], bias2[2]);
        oH.y = add2(acc2[i][3], bias2[3]);
        *(ulonglong2*)dst = oL;
        *(ulonglong2*)(dst + 4) = oH;
    }
}

// ------------------------------- clustered recurrence --------------------------
// 16 clusters x 8 CTAs x 512 threads. Cluster c owns batches {2c, 2c+1}.
// h buffers use INTERLEAVED layout [j][b]: idx = j*2 + b. GEMM packs f32x2 over
// GATE pairs (adjacent in g_Wh). Broadcast: 2 senders/warp publish (b0,b1) h
// pairs as single st.async.b64 -> 256 x 8B messages per CTA-step (was 512 x 4B).
// Sync protocol identical to the passing R6 kernel (full/empty mbarriers).
__global__ __launch_bounds__(512, 1) __cluster_dims__(8, 1, 1)
void lstm_rec(const float* __restrict__ h0, const float* __restrict__ c0,
              float* __restrict__ out, int write_finals) {
    __shared__ __align__(16) float h_s[2][2 * Hsz];     // [buf][j*2 + b]
    __shared__ __align__(8) ull mbar[4];                // full0 full1 empty0 empty1
    __shared__ unsigned s_rh[8], s_rmb[8];              // remote bases per rank

    int tid = threadIdx.x;
    int clu = blockIdx.x >> 3;
    int w = tid >> 5;
    int lane = tid & 31;
    unsigned rank;
    asm("mov.u32 %0, %%cluster_ctarank;" : "=r"(rank));

    unsigned my_hs = (unsigned)__cvta_generic_to_shared(h_s);
    unsigned my_mb = (unsigned)__cvta_generic_to_shared(mbar);

    if (tid == 0) {
        mbar_init(my_mb + 0, 1);    // full[0]
        mbar_init(my_mb + 8, 1);    // full[1]
        mbar_init(my_mb + 16, 8);   // empty[0]
        mbar_init(my_mb + 24, 8);   // empty[1]
        mbar_expect_tx(my_mb + 8, 2048);   // pre-arm full[1] for step-0 stores
    }
    if (tid < 8) {
        unsigned a;
        asm("mapa.shared::cluster.u32 %0, %1, %2;" : "=r"(a) : "r"(my_hs), "r"(tid));
        s_rh[tid] = a;
        asm("mapa.shared::cluster.u32 %0, %1, %2;" : "=r"(a) : "r"(my_mb), "r"(tid));
        s_rmb[tid] = a;            // +p*8 = full[p], +16+p*8 = empty[p]
    }

    int jg0 = (int)rank * 32 + w * 2;   // first of this warp's two global j's

    // weights, gate-pair packed: wg[kk][jj][gp] = (Wh[8l+kk][4(jg0+jj)+2gp],
    //                                              Wh[8l+kk][4(jg0+jj)+2gp+1])
    ull wg[8][2][2];
    #pragma unroll
    for (int kk = 0; kk < 8; kk++) {
        const float* row = g_Wh + (size_t)(8 * lane + kk) * Msz + 4 * jg0;
        ulonglong2 a = *(const ulonglong2*)row;
        ulonglong2 b = *(const ulonglong2*)(row + 4);
        wg[kk][0][0] = a.x; wg[kk][0][1] = a.y;
        wg[kk][1][0] = b.x; wg[kk][1][1] = b.y;
    }

    // lane's value id: v = lane>>1 = b*8 + jj*4 + g
    int v_me = lane >> 1;
    int b_me = v_me >> 3;
    int o_me = v_me & 7;
    int jj_me = o_me >> 2, g_me = o_me & 3;
    int jg_me = jg0 + jj_me;
    int bg_me = clu * 2 + b_me;
    bool owner = ((lane & 7) == 0);     // lanes 0,8,16,24
    bool sender = (lane == 0) || (lane == 8);   // b_me==0 owners; partner = lane+16

    // init h0 into buf 0, interleaved layout: h_s[0][j*2+b]
    h_s[0][tid] = h0[(clu * 2 + (tid & 1)) * Hsz + (tid >> 1)];

    float c_val = owner ? c0[bg_me * Hsz + jg_me] : 0.f;
    float xv = g_xp[(size_t)bg_me * Msz + jg_me * 4 + g_me];   // t=0

    float* out_hj = out + (size_t)bg_me * Ssz * Hsz + jg_me;
    const float* xp_bj = g_xp + (size_t)bg_me * Msz + jg_me * 4 + g_me;
    const size_t fin_off = (size_t)Bsz * Ssz * Hsz;

    __syncthreads();
    asm volatile("barrier.cluster.arrive.aligned;" ::: "memory");
    asm volatile("barrier.cluster.wait.aligned;" ::: "memory");

    for (int t = 0; t < Ssz; t++) {
        int cur = t & 1, nb = cur ^ 1;
        unsigned par = ((unsigned)(t - 1) >> 1) & 1u;
        bool not_last = (t + 1 < Ssz);

        if (t) mbar_wait(my_mb + cur * 8, par);     // full[cur]: data landed

        const float* hb = &h_s[cur][0];

        // one 64B block per lane = both batches' h for k in [8l, 8l+8)
        ulonglong2 q0 = *(const ulonglong2*)(hb + 16 * lane);
        ulonglong2 q1 = *(const ulonglong2*)(hb + 16 * lane + 4);
        ulonglong2 q2 = *(const ulonglong2*)(hb + 16 * lane + 8);
        ulonglong2 q3 = *(const ulonglong2*)(hb + 16 * lane + 12);
        ull hw[8] = {q0.x, q0.y, q1.x, q1.y, q2.x, q2.y, q3.x, q3.y};

        ull acc2[2][2][2];   // [b][jj][gp]
        #pragma unroll
        for (int b = 0; b < 2; b++)
            #pragma unroll
            for (int jj = 0; jj < 2; jj++)
                #pragma unroll
                for (int gp = 0; gp < 2; gp++) acc2[b][jj][gp] = 0ull;

        #pragma unroll
        for (int kk = 0; kk < 8; kk++) {
            float h0k, h1k; unpack2(h0k, h1k, hw[kk]);
            ull hb0 = pack2(h0k, h0k);
            ull hb1 = pack2(h1k, h1k);
            #pragma unroll
            for (int jj = 0; jj < 2; jj++)
                #pragma unroll
                for (int gp = 0; gp < 2; gp++) {
                    fma2(acc2[0][jj][gp], wg[kk][jj][gp], hb0);
                    fma2(acc2[1][jj][gp], wg[kk][jj][gp], hb1);
                }
        }

        float acc[16];   // v = b*8 + jj*4 + g
        #pragma unroll
        for (int b = 0; b < 2; b++)
            #pragma unroll
            for (int jj = 0; jj < 2; jj++)
                #pragma unroll
                for (int gp = 0; gp < 2; gp++)
                    unpack2(acc[b * 8 + jj * 4 + 2 * gp],
                            acc[b * 8 + jj * 4 + 2 * gp + 1], acc2[b][jj][gp]);

        __syncthreads();   // all warps done reading buf[cur]

        if (not_last && tid == 0) {
            mbar_expect_tx(my_mb + cur * 8, 2048);  // re-arm full[cur] for t+2
            #pragma unroll
            for (int r = 0; r < 8; r++)             // tell peers buf[cur] is free
                asm volatile("mbarrier.arrive.shared::cluster.b64 _, [%0];"
                             :: "r"(s_rmb[r] + 16u + (unsigned)cur * 8u) : "memory");
        }

        // butterfly: 16 values over 32 lanes; lane L ends with value (L>>1)
        int cnt = 16;
        #pragma unroll
        for (int off = 16; off >= 2; off >>= 1) {
            cnt >>= 1;
            bool upper = (lane & off) != 0;
            #pragma unroll
            for (int v = 0; v < cnt; v++) {
                float send = upper ? acc[v] : acc[v + cnt];
                float recv = __shfl_xor_sync(0xffffffffu, send, off);
                acc[v] = (upper ? acc[v + cnt] : acc[v]) + recv;
            }
        }
        acc[0] += __shfl_xor_sync(0xffffffffu, acc[0], 1);

        float pre = acc[0] + xv;
        float a;
        if (g_me == 2) { float e = __expf(-2.f * pre); a = __fdividef(2.f, 1.f + e) - 1.f; }
        else           { a = __fdividef(1.f, 1.f + __expf(-pre)); }

        int base = lane & ~7;
        float fg = __shfl_sync(0xffffffffu, a, base);
        float ig = __shfl_sync(0xffffffffu, a, base + 2);
        float cg = __shfl_sync(0xffffffffu, a, base + 4);
        float og = __shfl_sync(0xffffffffu, a, base + 6);

        float hn = 0.f;
        if (owner) {
            c_val = c_val * fg + ig * cg;
            float e = __expf(-2.f * c_val);
            hn = og * (__fdividef(2.f, 1.f + e) - 1.f);
            out_hj[(size_t)t * Hsz] = hn;
            if (!not_last && write_finals) {
                out[fin_off + (size_t)bg_me * Hsz + jg_me] = hn;                          // h_f
                out[fin_off + (size_t)Bsz * Hsz + (size_t)bg_me * Hsz + jg_me] = c_val;   // c_f
            }
        }

        // partner (b1) value down to the b0 sender lanes
        float hn_p = __shfl_down_sync(0xffffffffu, hn, 16);

        if (not_last) {
            xv = __ldg(xp_bj + (size_t)(t + 1) * Bsz * Msz);   // overlaps empty wait
            if (t) mbar_wait(my_mb + 16 + nb * 8, par);        // peers done reading buf[nb]
            if (sender) {
                // one b64 = (h[j][b0], h[j][b1]) at interleaved idx 2*jg_me
                unsigned off4 = (unsigned)(nb * (2 * Hsz) + 2 * jg_me) * 4u;
                ull vbits = pack2(hn, hn_p);
                #pragma unroll
                for (int r = 0; r < 8; r++)
                    asm volatile(
                        "st.async.weak.shared::cluster.mbarrier::complete_tx::bytes.b64 [%0], %1, [%2];"
                        :: "r"(s_rh[r] + off4), "l"(vbits),
                           "r"(s_rmb[r] + (unsigned)nb * 8u) : "memory");
            }
        }
    }

    // lifetime safety: no CTA exits while cluster peers may have ops in flight
    asm volatile("barrier.cluster.arrive.aligned;" ::: "memory");
    asm volatile("barrier.cluster.wait.aligned;" ::: "memory");
}

// ------------------------------- launch ----------------------------------------
extern "C" void kernel_launch(void* const* d_in, const int* in_sizes, int n_in,
                              void* d_out, int out_size) {
    const float* x  = (const float*)d_in[0];
    const float* h0 = (const float*)d_in[1];
    const float* c0 = (const float*)d_in[2];
    const float* Wf = (const float*)d_in[3];
    const float* bf = (const float*)d_in[4];
    const float* Wi = (const float*)d_in[5];
    const float* bi = (const float*)d_in[6];
    const float* Wc = (const float*)d_in[7];
    const float* bc = (const float*)d_in[8];
    const float* Wo = (const float*)d_in[9];
    const float* bo = (const float*)d_in[10];
    float* out = (float*)d_out;

    int full = Bsz * Ssz * Hsz + 2 * Bsz * Hsz;
    int write_finals = (out_size >= full) ? 1 : 0;

    pack_kernel<<<512, 256>>>(Wf, Wi, Wc, Wo, bf, bi, bc, bo);

    dim3 grid_x(8, 512);
    xproj_kernel<<<grid_x, 256>>>(x);

    lstm_rec<<<128, 512>>>(h0, c0, out, write_finals);
}

// round 9
// speedup vs baseline: 1.9622x; 1.9622x over previous
#include <cuda_runtime.h>
#include <math.h>
#include <stdint.h>

#define Bsz 32
#define Ssz 2048
#define Isz 256
#define Hsz 256
#define Msz 1024   // 4*H, packed as m = j*4 + g  (g: 0=f,1=i,2=c,3=o)

typedef unsigned long long ull;

// ------------------------------- f32x2 helpers ---------------------------------
__device__ __forceinline__ ull pack2(float lo, float hi) {
    ull r; asm("mov.b64 %0, {%1,%2};" : "=l"(r) : "f"(lo), "f"(hi)); return r;
}
__device__ __forceinline__ void unpack2(float& lo, float& hi, ull v) {
    asm("mov.b64 {%0,%1}, %2;" : "=f"(lo), "=f"(hi) : "l"(v));
}
__device__ __forceinline__ void fma2(ull& d, ull a, ull b) {
    asm("fma.rn.f32x2 %0, %1, %2, %0;" : "+l"(d) : "l"(a), "l"(b));
}
__device__ __forceinline__ ull add2(ull a, ull b) {
    ull r; asm("add.rn.f32x2 %0, %1, %2;" : "=l"(r) : "l"(a), "l"(b)); return r;
}

// ------------------------------- mbarrier helpers ------------------------------
__device__ __forceinline__ void mbar_init(unsigned addr, unsigned count) {
    asm volatile("mbarrier.init.shared.b64 [%0], %1;" :: "r"(addr), "r"(count) : "memory");
}
__device__ __forceinline__ void mbar_expect_tx(unsigned addr, unsigned bytes) {
    asm volatile("mbarrier.arrive.expect_tx.shared.b64 _, [%0], %1;"
                 :: "r"(addr), "r"(bytes) : "memory");
}
__device__ __forceinline__ void mbar_wait(unsigned addr, unsigned parity) {
    unsigned done;
    asm volatile(
        "{\n\t.reg .pred p;\n\t"
        "mbarrier.try_wait.parity.acquire.cta.shared::cta.b64 p, [%1], %2;\n\t"
        "selp.b32 %0, 1, 0, p;\n\t}"
        : "=r"(done) : "r"(addr), "r"(parity) : "memory");
    if (!done) {
        asm volatile(
            "{\n\t.reg .pred P1;\n\t"
            "WL_%=:\n\t"
            "mbarrier.try_wait.parity.acquire.cta.shared::cta.b64 P1, [%0], %1, 0x989680;\n\t"
            "@P1 bra.uni WD_%=;\n\t"
            "bra.uni WL_%=;\n\t"
            "WD_%=:\n\t}"
            :: "r"(addr), "r"(parity) : "memory");
    }
}

// ------------------------------- device scratch -------------------------------
__device__ float g_Wx[Isz * Msz];                      // [k][m], x-part rows of W
__device__ float g_Wh[Hsz * Msz];                      // [k][m], h-part rows of W
__device__ float g_bias[Msz];
__device__ float g_xp[(size_t)Bsz * Ssz * Msz];        // [t][b][m]  (256 MB)

// ------------------------------- pack ------------------------------------------
__global__ void pack_kernel(const float* __restrict__ Wf, const float* __restrict__ Wi,
                            const float* __restrict__ Wc, const float* __restrict__ Wo,
                            const float* __restrict__ bf, const float* __restrict__ bi,
                            const float* __restrict__ bc, const float* __restrict__ bo) {
    int idx = blockIdx.x * blockDim.x + threadIdx.x;   // over (k in 0..511, j in 0..255)
    if (idx < 512 * 256) {
        int k = idx >> 8;      // row of W_all (0..511): [0,256) = h-part, [256,512) = x-part
        int j = idx & 255;
        const float* W[4] = {Wf, Wi, Wc, Wo};
        #pragma unroll
        for (int g = 0; g < 4; g++) {
            float v = W[g][k * Hsz + j];
            int m = j * 4 + g;
            if (k < Hsz) g_Wh[k * Msz + m] = v;
            else         g_Wx[(k - Hsz) * Msz + m] = v;
        }
        if (k == 0) {
            const float* bias[4] = {bf, bi, bc, bo};
            #pragma unroll
            for (int g = 0; g < 4; g++) g_bias[j * 4 + g] = bias[g][j];
        }
    }
}

// ------------------------------- xproj GEMM (f32x2) ----------------------------
#define XBM 128
#define XBN 128
#define XBK 8

__global__ __launch_bounds__(256) void xproj_kernel(const float* __restrict__ x) {
    __shared__ float As[XBK][XBM + 4];
    __shared__ float Bs[XBK][XBN];

    int bn = blockIdx.x;               // 0..7    (m blocks)
    int bm = blockIdx.y;               // 0..511  (row blocks)
    int tid = threadIdx.x;
    int tx = tid & 15;
    int ty = tid >> 4;

    int r0 = bm * XBM;
    int m0 = bn * XBN;

    int arow = tid >> 1, akq = tid & 1;
    int r = r0 + arow;
    int b = r & 31, t = r >> 5;
    const float* arow_ptr = x + ((size_t)b * Ssz + t) * Isz;

    int bk = tid >> 5, bmq = tid & 31;
    const float* brow_ptr = g_Wx + (size_t)bk * Msz + m0 + bmq * 4;

    ull acc2[8][4];
    #pragma unroll
    for (int i = 0; i < 8; i++)
        #pragma unroll
        for (int jp = 0; jp < 4; jp++) acc2[i][jp] = 0ull;

    for (int k0 = 0; k0 < Isz; k0 += XBK) {
        float4 av = *(const float4*)(arow_ptr + k0 + akq * 4);
        As[akq * 4 + 0][arow] = av.x;
        As[akq * 4 + 1][arow] = av.y;
        As[akq * 4 + 2][arow] = av.z;
        As[akq * 4 + 3][arow] = av.w;
        *(float4*)&Bs[bk][bmq * 4] = *(const float4*)(brow_ptr + (size_t)k0 * Msz);
        __syncthreads();
        #pragma unroll
        for (int kk = 0; kk < XBK; kk++) {
            float4 aA = *(float4*)&As[kk][ty * 8];
            float4 aB = *(float4*)&As[kk][ty * 8 + 4];
            ulonglong2 bL = *(ulonglong2*)&Bs[kk][tx * 8];
            ulonglong2 bH = *(ulonglong2*)&Bs[kk][tx * 8 + 4];
            ull b2[4] = {bL.x, bL.y, bH.x, bH.y};
            float ar[8] = {aA.x, aA.y, aA.z, aA.w, aB.x, aB.y, aB.z, aB.w};
            #pragma unroll
            for (int i = 0; i < 8; i++) {
                ull a2 = pack2(ar[i], ar[i]);
                #pragma unroll
                for (int jp = 0; jp < 4; jp++) fma2(acc2[i][jp], a2, b2[jp]);
            }
        }
        __syncthreads();
    }

    ull bias2[4];
    {
        ulonglong2 bL = *(const ulonglong2*)(g_bias + m0 + tx * 8);
        ulonglong2 bH = *(const ulonglong2*)(g_bias + m0 + tx * 8 + 4);
        bias2[0] = bL.x; bias2[1] = bL.y; bias2[2] = bH.x; bias2[3] = bH.y;
    }
    #pragma unroll
    for (int i = 0; i < 8; i++) {
        int rr = r0 + ty * 8 + i;
        float* dst = g_xp + (size_t)rr * Msz + m0 + tx * 8;
        ulonglong2 oL, oH;
        oL.x = add2(acc2[i][0], bias2[0]);
        oL.y = add2(acc2[i][1], bias2[1]);
        oH.x = add2(acc2[i][2], bias2[2]);
        oH.y = add2(acc2[i][3], bias2[3]);
        *(ulonglong2*)dst = oL;
        *(ulonglong2*)(dst + 4) = oH;
    }
}

// ------------------------------- clustered recurrence --------------------------
// 16 clusters x 8 CTAs x 256 threads (8 warps). Cluster c owns batches
// {2c, 2c+1}; CTA rank r owns j in [32r, 32r+32); warp w owns 4 j's for both
// batches; lane l owns k in {l+32i, i=0..7} (strided -> conflict-free LDS.32).
// Weights register-resident, k-pair packed: 64 ull/thread. 256 threads ->
// 256-reg budget: NO SPILLS (the 512-thread variants spilled weights to local
// every step). 32-value butterfly; sync protocol identical to passing R6
// mbarrier kernel (full/empty, 4B st.async, [b][j] layout).
__global__ __launch_bounds__(256, 1) __cluster_dims__(8, 1, 1)
void lstm_rec(const float* __restrict__ h0, const float* __restrict__ c0,
              float* __restrict__ out, int write_finals) {
    __shared__ __align__(16) float h_s[2][2 * Hsz];     // [buf][b_local*256 + j]
    __shared__ __align__(8) ull mbar[4];                // full0 full1 empty0 empty1
    __shared__ unsigned s_rh[8], s_rmb[8];              // remote bases per rank

    int tid = threadIdx.x;
    int clu = blockIdx.x >> 3;
    int w = tid >> 5;
    int lane = tid & 31;
    unsigned rank;
    asm("mov.u32 %0, %%cluster_ctarank;" : "=r"(rank));

    unsigned my_hs = (unsigned)__cvta_generic_to_shared(h_s);
    unsigned my_mb = (unsigned)__cvta_generic_to_shared(mbar);

    if (tid == 0) {
        mbar_init(my_mb + 0, 1);    // full[0]
        mbar_init(my_mb + 8, 1);    // full[1]
        mbar_init(my_mb + 16, 8);   // empty[0]
        mbar_init(my_mb + 24, 8);   // empty[1]
        mbar_expect_tx(my_mb + 8, 2048);   // pre-arm full[1] for step-0 stores
    }
    if (tid < 8) {
        unsigned a;
        asm("mapa.shared::cluster.u32 %0, %1, %2;" : "=r"(a) : "r"(my_hs), "r"(tid));
        s_rh[tid] = a;
        asm("mapa.shared::cluster.u32 %0, %1, %2;" : "=r"(a) : "r"(my_mb), "r"(tid));
        s_rmb[tid] = a;            // +p*8 = full[p], +16+p*8 = empty[p]
    }

    int jg0 = (int)rank * 32 + w * 4;   // first of this warp's FOUR global j's

    // weights, k-pair packed over strided k:
    // wkp[p][jj*4+g] = (Wh[l+64p][4(jg0+jj)+g], Wh[l+64p+32][4(jg0+jj)+g])
    ull wkp[4][16];
    #pragma unroll
    for (int p = 0; p < 4; p++) {
        const float* rA = g_Wh + (size_t)(lane + 64 * p) * Msz;
        const float* rB = g_Wh + (size_t)(lane + 64 * p + 32) * Msz;
        #pragma unroll
        for (int jj = 0; jj < 4; jj++) {
            float4 a = *(const float4*)(rA + 4 * (jg0 + jj));
            float4 b = *(const float4*)(rB + 4 * (jg0 + jj));
            wkp[p][jj * 4 + 0] = pack2(a.x, b.x);
            wkp[p][jj * 4 + 1] = pack2(a.y, b.y);
            wkp[p][jj * 4 + 2] = pack2(a.z, b.z);
            wkp[p][jj * 4 + 3] = pack2(a.w, b.w);
        }
    }

    // lane's value id: v = lane = b*16 + jj*4 + g
    int b_me = lane >> 4;
    int jj_me = (lane >> 2) & 3;
    int g_me = lane & 3;
    int jg_me = jg0 + jj_me;
    int bg_me = clu * 2 + b_me;
    bool owner = (g_me == 0);           // 8 owners per warp

    // init h0 into buf 0 (local copy: 2 batches x 256 j), 2 entries per thread
    {
        int i0 = tid, i1 = tid + 256;
        h_s[0][i0] = h0[(clu * 2 + (i0 >> 8)) * Hsz + (i0 & 255)];
        h_s[0][i1] = h0[(clu * 2 + (i1 >> 8)) * Hsz + (i1 & 255)];
    }
    float c_val = owner ? c0[bg_me * Hsz + jg_me] : 0.f;
    float xv = g_xp[(size_t)bg_me * Msz + jg_me * 4 + g_me];   // t=0

    float* out_hj = out + (size_t)bg_me * Ssz * Hsz + jg_me;
    const float* xp_bj = g_xp + (size_t)bg_me * Msz + jg_me * 4 + g_me;
    const size_t fin_off = (size_t)Bsz * Ssz * Hsz;

    __syncthreads();
    asm volatile("barrier.cluster.arrive.aligned;" ::: "memory");
    asm volatile("barrier.cluster.wait.aligned;" ::: "memory");

    for (int t = 0; t < Ssz; t++) {
        int cur = t & 1, nb = cur ^ 1;
        unsigned par = ((unsigned)(t - 1) >> 1) & 1u;
        bool not_last = (t + 1 < Ssz);

        if (t) mbar_wait(my_mb + cur * 8, par);     // full[cur]: data landed

        float acc[32];   // v = b*16 + jj*4 + g

        #pragma unroll
        for (int b = 0; b < 2; b++) {
            const float* hb = &h_s[cur][b * Hsz];
            // strided conflict-free loads: lane l -> bank l
            float hv[8];
            #pragma unroll
            for (int i = 0; i < 8; i++) hv[i] = hb[lane + 32 * i];
            ull hp[4];
            #pragma unroll
            for (int p = 0; p < 4; p++) hp[p] = pack2(hv[2 * p], hv[2 * p + 1]);

            ull acc2[16];
            #pragma unroll
            for (int m = 0; m < 16; m++) acc2[m] = 0ull;
            #pragma unroll
            for (int p = 0; p < 4; p++)
                #pragma unroll
                for (int m = 0; m < 16; m++) fma2(acc2[m], wkp[p][m], hp[p]);

            #pragma unroll
            for (int m = 0; m < 16; m++) {
                float lo, hi; unpack2(lo, hi, acc2[m]);
                acc[b * 16 + m] = lo + hi;
            }
        }

        __syncthreads();   // all warps done reading buf[cur]

        if (not_last && tid == 0) {
            mbar_expect_tx(my_mb + cur * 8, 2048);  // re-arm full[cur] for t+2
            #pragma unroll
            for (int r = 0; r < 8; r++)             // tell peers buf[cur] is free
                asm volatile("mbarrier.arrive.shared::cluster.b64 _, [%0];"
                             :: "r"(s_rmb[r] + 16u + (unsigned)cur * 8u) : "memory");
        }

        // butterfly: 32 values over 32 lanes; lane L ends with full sum of value L
        int cnt = 32;
        #pragma unroll
        for (int off = 16; off >= 1; off >>= 1) {
            cnt >>= 1;
            bool upper = (lane & off) != 0;
            #pragma unroll
            for (int v = 0; v < cnt; v++) {
                float send = upper ? acc[v] : acc[v + cnt];
                float recv = __shfl_xor_sync(0xffffffffu, send, off);
                acc[v] = (upper ? acc[v + cnt] : acc[v]) + recv;
            }
        }

        float pre = acc[0] + xv;
        float a;
        if (g_me == 2) { float e = __expf(-2.f * pre); a = __fdividef(2.f, 1.f + e) - 1.f; }
        else           { a = __fdividef(1.f, 1.f + __expf(-pre)); }

        int base = lane & ~3;
        float fg = __shfl_sync(0xffffffffu, a, base);
        float ig = __shfl_sync(0xffffffffu, a, base + 1);
        float cg = __shfl_sync(0xffffffffu, a, base + 2);
        float og = __shfl_sync(0xffffffffu, a, base + 3);

        float hn = 0.f;
        if (owner) {
            c_val = c_val * fg + ig * cg;
            float e = __expf(-2.f * c_val);
            hn = og * (__fdividef(2.f, 1.f + e) - 1.f);
            out_hj[(size_t)t * Hsz] = hn;
            if (!not_last && write_finals) {
                out[fin_off + (size_t)bg_me * Hsz + jg_me] = hn;                          // h_f
                out[fin_off + (size_t)Bsz * Hsz + (size_t)bg_me * Hsz + jg_me] = c_val;   // c_f
            }
        }

        if (not_last) {
            xv = __ldg(xp_bj + (size_t)(t + 1) * Bsz * Msz);   // overlaps empty wait
            if (t) mbar_wait(my_mb + 16 + nb * 8, par);        // peers done reading buf[nb]
            if (owner) {
                unsigned off4 = (unsigned)(nb * (2 * Hsz) + b_me * Hsz + jg_me) * 4u;
                unsigned hbits = __float_as_uint(hn);
                #pragma unroll
                for (int r = 0; r < 8; r++)
                    asm volatile(
                        "st.async.weak.shared::cluster.mbarrier::complete_tx::bytes.b32 [%0], %1, [%2];"
                        :: "r"(s_rh[r] + off4), "r"(hbits),
                           "r"(s_rmb[r] + (unsigned)nb * 8u) : "memory");
            }
        }
    }

    // lifetime safety: no CTA exits while cluster peers may have ops in flight
    asm volatile("barrier.cluster.arrive.aligned;" ::: "memory");
    asm volatile("barrier.cluster.wait.aligned;" ::: "memory");
}

// ------------------------------- launch ----------------------------------------
extern "C" void kernel_launch(void* const* d_in, const int* in_sizes, int n_in,
                              void* d_out, int out_size) {
    const float* x  = (const float*)d_in[0];
    const float* h0 = (const float*)d_in[1];
    const float* c0 = (const float*)d_in[2];
    const float* Wf = (const float*)d_in[3];
    const float* bf = (const float*)d_in[4];
    const float* Wi = (const float*)d_in[5];
    const float* bi = (const float*)d_in[6];
    const float* Wc = (const float*)d_in[7];
    const float* bc = (const float*)d_in[8];
    const float* Wo = (const float*)d_in[9];
    const float* bo = (const float*)d_in[10];
    float* out = (float*)d_out;

    int full = Bsz * Ssz * Hsz + 2 * Bsz * Hsz;
    int write_finals = (out_size >= full) ? 1 : 0;

    pack_kernel<<<512, 256>>>(Wf, Wi, Wc, Wo, bf, bi, bc, bo);

    dim3 grid_x(8, 512);
    xproj_kernel<<<grid_x, 256>>>(x);

    lstm_rec<<<128, 256>>>(h0, c0, out, write_finals);
}

// round 10
// speedup vs baseline: 2.0341x; 1.0367x over previous
#include <cuda_runtime.h>
#include <math.h>
#include <stdint.h>

#define Bsz 32
#define Ssz 2048
#define Isz 256
#define Hsz 256
#define Msz 1024   // 4*H, packed as m = j*4 + g  (g: 0=f,1=i,2=c,3=o)

typedef unsigned long long ull;

// ------------------------------- f32x2 helpers ---------------------------------
__device__ __forceinline__ ull pack2(float lo, float hi) {
    ull r; asm("mov.b64 %0, {%1,%2};" : "=l"(r) : "f"(lo), "f"(hi)); return r;
}
__device__ __forceinline__ void unpack2(float& lo, float& hi, ull v) {
    asm("mov.b64 {%0,%1}, %2;" : "=f"(lo), "=f"(hi) : "l"(v));
}
__device__ __forceinline__ void fma2(ull& d, ull a, ull b) {
    asm("fma.rn.f32x2 %0, %1, %2, %0;" : "+l"(d) : "l"(a), "l"(b));
}
__device__ __forceinline__ ull add2(ull a, ull b) {
    ull r; asm("add.rn.f32x2 %0, %1, %2;" : "=l"(r) : "l"(a), "l"(b)); return r;
}

// ------------------------------- mbarrier helpers ------------------------------
__device__ __forceinline__ void mbar_init(unsigned addr, unsigned count) {
    asm volatile("mbarrier.init.shared.b64 [%0], %1;" :: "r"(addr), "r"(count) : "memory");
}
__device__ __forceinline__ void mbar_expect_tx(unsigned addr, unsigned bytes) {
    asm volatile("mbarrier.arrive.expect_tx.shared.b64 _, [%0], %1;"
                 :: "r"(addr), "r"(bytes) : "memory");
}
__device__ __forceinline__ void mbar_wait(unsigned addr, unsigned parity) {
    unsigned done;
    asm volatile(
        "{\n\t.reg .pred p;\n\t"
        "mbarrier.try_wait.parity.acquire.cta.shared::cta.b64 p, [%1], %2;\n\t"
        "selp.b32 %0, 1, 0, p;\n\t}"
        : "=r"(done) : "r"(addr), "r"(parity) : "memory");
    if (!done) {
        asm volatile(
            "{\n\t.reg .pred P1;\n\t"
            "WL_%=:\n\t"
            "mbarrier.try_wait.parity.acquire.cta.shared::cta.b64 P1, [%0], %1, 0x989680;\n\t"
            "@P1 bra.uni WD_%=;\n\t"
            "bra.uni WL_%=;\n\t"
            "WD_%=:\n\t}"
            :: "r"(addr), "r"(parity) : "memory");
    }
}

// ------------------------------- device scratch -------------------------------
__device__ float g_Wx[Isz * Msz];                      // [k][m], x-part rows of W
__device__ float g_Wh[Hsz * Msz];                      // [k][m], h-part rows of W
__device__ float g_bias[Msz];
__device__ float g_xp[(size_t)Bsz * Ssz * Msz];        // [t][b][m]  (256 MB)

// ------------------------------- pack ------------------------------------------
__global__ void pack_kernel(const float* __restrict__ Wf, const float* __restrict__ Wi,
                            const float* __restrict__ Wc, const float* __restrict__ Wo,
                            const float* __restrict__ bf, const float* __restrict__ bi,
                            const float* __restrict__ bc, const float* __restrict__ bo) {
    int idx = blockIdx.x * blockDim.x + threadIdx.x;   // over (k in 0..511, j in 0..255)
    if (idx < 512 * 256) {
        int k = idx >> 8;      // row of W_all (0..511): [0,256) = h-part, [256,512) = x-part
        int j = idx & 255;
        const float* W[4] = {Wf, Wi, Wc, Wo};
        #pragma unroll
        for (int g = 0; g < 4; g++) {
            float v = W[g][k * Hsz + j];
            int m = j * 4 + g;
            if (k < Hsz) g_Wh[k * Msz + m] = v;
            else         g_Wx[(k - Hsz) * Msz + m] = v;
        }
        if (k == 0) {
            const float* bias[4] = {bf, bi, bc, bo};
            #pragma unroll
            for (int g = 0; g < 4; g++) g_bias[j * 4 + g] = bias[g][j];
        }
    }
}

// ------------------------------- xproj GEMM (f32x2) ----------------------------
#define XBM 128
#define XBN 128
#define XBK 8

__global__ __launch_bounds__(256) void xproj_kernel(const float* __restrict__ x) {
    __shared__ float As[XBK][XBM + 4];
    __shared__ float Bs[XBK][XBN];

    int bn = blockIdx.x;               // 0..7    (m blocks)
    int bm = blockIdx.y;               // 0..511  (row blocks)
    int tid = threadIdx.x;
    int tx = tid & 15;
    int ty = tid >> 4;

    int r0 = bm * XBM;
    int m0 = bn * XBN;

    int arow = tid >> 1, akq = tid & 1;
    int r = r0 + arow;
    int b = r & 31, t = r >> 5;
    const float* arow_ptr = x + ((size_t)b * Ssz + t) * Isz;

    int bk = tid >> 5, bmq = tid & 31;
    const float* brow_ptr = g_Wx + (size_t)bk * Msz + m0 + bmq * 4;

    ull acc2[8][4];
    #pragma unroll
    for (int i = 0; i < 8; i++)
        #pragma unroll
        for (int jp = 0; jp < 4; jp++) acc2[i][jp] = 0ull;

    for (int k0 = 0; k0 < Isz; k0 += XBK) {
        float4 av = *(const float4*)(arow_ptr + k0 + akq * 4);
        As[akq * 4 + 0][arow] = av.x;
        As[akq * 4 + 1][arow] = av.y;
        As[akq * 4 + 2][arow] = av.z;
        As[akq * 4 + 3][arow] = av.w;
        *(float4*)&Bs[bk][bmq * 4] = *(const float4*)(brow_ptr + (size_t)k0 * Msz);
        __syncthreads();
        #pragma unroll
        for (int kk = 0; kk < XBK; kk++) {
            float4 aA = *(float4*)&As[kk][ty * 8];
            float4 aB = *(float4*)&As[kk][ty * 8 + 4];
            ulonglong2 bL = *(ulonglong2*)&Bs[kk][tx * 8];
            ulonglong2 bH = *(ulonglong2*)&Bs[kk][tx * 8 + 4];
            ull b2[4] = {bL.x, bL.y, bH.x, bH.y};
            float ar[8] = {aA.x, aA.y, aA.z, aA.w, aB.x, aB.y, aB.z, aB.w};
            #pragma unroll
            for (int i = 0; i < 8; i++) {
                ull a2 = pack2(ar[i], ar[i]);
                #pragma unroll
                for (int jp = 0; jp < 4; jp++) fma2(acc2[i][jp], a2, b2[jp]);
            }
        }
        __syncthreads();
    }

    ull bias2[4];
    {
        ulonglong2 bL = *(const ulonglong2*)(g_bias + m0 + tx * 8);
        ulonglong2 bH = *(const ulonglong2*)(g_bias + m0 + tx * 8 + 4);
        bias2[0] = bL.x; bias2[1] = bL.y; bias2[2] = bH.x; bias2[3] = bH.y;
    }
    #pragma unroll
    for (int i = 0; i < 8; i++) {
        int rr = r0 + ty * 8 + i;
        float* dst = g_xp + (size_t)rr * Msz + m0 + tx * 8;
        ulonglong2 oL, oH;
        oL.x = add2(acc2[i][0], bias2[0]);
        oL.y = add2(acc2[i][1], bias2[1]);
        oH.x = add2(acc2[i][2], bias2[2]);
        oH.y = add2(acc2[i][3], bias2[3]);
        *(ulonglong2*)dst = oL;
        *(ulonglong2*)(dst + 4) = oH;
    }
}

// ------------------------------- clustered recurrence --------------------------
// 16 clusters x 8 CTAs x 256 threads (8 warps). Same compute layout as the R9
// winner (strided-k, register weights, 32-value butterfly). NEW: 4-deep h ring
// buffer -> the producer's empty-wait has 3 steps of slack (fabric RTT off the
// critical path), and st.async broadcast is issued immediately after hn.
__global__ __launch_bounds__(256, 1) __cluster_dims__(8, 1, 1)
void lstm_rec(const float* __restrict__ h0, const float* __restrict__ c0,
              float* __restrict__ out, int write_finals) {
    __shared__ __align__(16) float h_s[4][2 * Hsz];     // [buf][b_local*256 + j]
    __shared__ __align__(8) ull mbar[8];                // full[0..3], empty[0..3]
    __shared__ unsigned s_rh[8], s_rmb[8];              // remote bases per rank

    int tid = threadIdx.x;
    int clu = blockIdx.x >> 3;
    int w = tid >> 5;
    int lane = tid & 31;
    unsigned rank;
    asm("mov.u32 %0, %%cluster_ctarank;" : "=r"(rank));

    unsigned my_hs = (unsigned)__cvta_generic_to_shared(h_s);
    unsigned my_mb = (unsigned)__cvta_generic_to_shared(mbar);
    // layout: full[b] at my_mb + b*8 ; empty[b] at my_mb + 32 + b*8

    if (tid == 0) {
        #pragma unroll
        for (int b = 0; b < 4; b++) {
            mbar_init(my_mb + b * 8, 1);        // full[b]
            mbar_init(my_mb + 32 + b * 8, 8);   // empty[b]
        }
        // pre-arm full[1..3] for stores during steps 0,1,2 (buf0 armed in-loop at t=0)
        mbar_expect_tx(my_mb + 8, 2048);
        mbar_expect_tx(my_mb + 16, 2048);
        mbar_expect_tx(my_mb + 24, 2048);
    }
    if (tid < 8) {
        unsigned a;
        asm("mapa.shared::cluster.u32 %0, %1, %2;" : "=r"(a) : "r"(my_hs), "r"(tid));
        s_rh[tid] = a;
        asm("mapa.shared::cluster.u32 %0, %1, %2;" : "=r"(a) : "r"(my_mb), "r"(tid));
        s_rmb[tid] = a;
    }

    int jg0 = (int)rank * 32 + w * 4;   // first of this warp's FOUR global j's

    // weights, k-pair packed over strided k:
    // wkp[p][jj*4+g] = (Wh[l+64p][4(jg0+jj)+g], Wh[l+64p+32][4(jg0+jj)+g])
    ull wkp[4][16];
    #pragma unroll
    for (int p = 0; p < 4; p++) {
        const float* rA = g_Wh + (size_t)(lane + 64 * p) * Msz;
        const float* rB = g_Wh + (size_t)(lane + 64 * p + 32) * Msz;
        #pragma unroll
        for (int jj = 0; jj < 4; jj++) {
            float4 a = *(const float4*)(rA + 4 * (jg0 + jj));
            float4 b = *(const float4*)(rB + 4 * (jg0 + jj));
            wkp[p][jj * 4 + 0] = pack2(a.x, b.x);
            wkp[p][jj * 4 + 1] = pack2(a.y, b.y);
            wkp[p][jj * 4 + 2] = pack2(a.z, b.z);
            wkp[p][jj * 4 + 3] = pack2(a.w, b.w);
        }
    }

    // lane's value id: v = lane = b*16 + jj*4 + g
    int b_me = lane >> 4;
    int jj_me = (lane >> 2) & 3;
    int g_me = lane & 3;
    int jg_me = jg0 + jj_me;
    int bg_me = clu * 2 + b_me;
    bool owner = (g_me == 0);           // 8 owners per warp

    // init h0 into buf 0 (local copy: 2 batches x 256 j), 2 entries per thread
    {
        int i0 = tid, i1 = tid + 256;
        h_s[0][i0] = h0[(clu * 2 + (i0 >> 8)) * Hsz + (i0 & 255)];
        h_s[0][i1] = h0[(clu * 2 + (i1 >> 8)) * Hsz + (i1 & 255)];
    }
    float c_val = owner ? c0[bg_me * Hsz + jg_me] : 0.f;
    float xv = g_xp[(size_t)bg_me * Msz + jg_me * 4 + g_me];   // t=0

    float* out_hj = out + (size_t)bg_me * Ssz * Hsz + jg_me;
    const float* xp_bj = g_xp + (size_t)bg_me * Msz + jg_me * 4 + g_me;
    const size_t fin_off = (size_t)Bsz * Ssz * Hsz;

    __syncthreads();
    asm volatile("barrier.cluster.arrive.aligned;" ::: "memory");
    asm volatile("barrier.cluster.wait.aligned;" ::: "memory");

    for (int t = 0; t < Ssz; t++) {
        int cur = t & 3, nb = (t + 1) & 3;
        bool not_last = (t + 1 < Ssz);

        if (t) mbar_wait(my_mb + cur * 8, ((unsigned)(t - 1) >> 2) & 1u);  // full[cur]

        float acc[32];   // v = b*16 + jj*4 + g

        #pragma unroll
        for (int b = 0; b < 2; b++) {
            const float* hb = &h_s[cur][b * Hsz];
            // strided conflict-free loads: lane l -> bank l
            float hv[8];
            #pragma unroll
            for (int i = 0; i < 8; i++) hv[i] = hb[lane + 32 * i];
            ull hp[4];
            #pragma unroll
            for (int p = 0; p < 4; p++) hp[p] = pack2(hv[2 * p], hv[2 * p + 1]);

            ull acc2[16];
            #pragma unroll
            for (int m = 0; m < 16; m++) acc2[m] = 0ull;
            #pragma unroll
            for (int p = 0; p < 4; p++)
                #pragma unroll
                for (int m = 0; m < 16; m++) fma2(acc2[m], wkp[p][m], hp[p]);

            #pragma unroll
            for (int m = 0; m < 16; m++) {
                float lo, hi; unpack2(lo, hi, acc2[m]);
                acc[b * 16 + m] = lo + hi;
            }
        }

        __syncthreads();   // all warps done reading buf[cur]

        if (tid == 0) {
            mbar_expect_tx(my_mb + cur * 8, 2048);  // re-arm full[cur] (reused at t+4)
            #pragma unroll
            for (int r = 0; r < 8; r++)             // release buf[cur] to producers (t+3)
                asm volatile("mbarrier.arrive.shared::cluster.b64 _, [%0];"
                             :: "r"(s_rmb[r] + 32u + (unsigned)cur * 8u) : "memory");
        }

        // prefetch next xp early: DRAM latency overlaps butterfly + activation
        float xv_next = 0.f;
        if (not_last) xv_next = __ldg(xp_bj + (size_t)(t + 1) * Bsz * Msz);

        // butterfly: 32 values over 32 lanes; lane L ends with full sum of value L
        int cnt = 32;
        #pragma unroll
        for (int off = 16; off >= 1; off >>= 1) {
            cnt >>= 1;
            bool upper = (lane & off) != 0;
            #pragma unroll
            for (int v = 0; v < cnt; v++) {
                float send = upper ? acc[v] : acc[v + cnt];
                float recv = __shfl_xor_sync(0xffffffffu, send, off);
                acc[v] = (upper ? acc[v + cnt] : acc[v]) + recv;
            }
        }

        float pre = acc[0] + xv;
        float a;
        if (g_me == 2) { float e = __expf(-2.f * pre); a = __fdividef(2.f, 1.f + e) - 1.f; }
        else           { a = __fdividef(1.f, 1.f + __expf(-pre)); }

        int base = lane & ~3;
        float fg = __shfl_sync(0xffffffffu, a, base);
        float ig = __shfl_sync(0xffffffffu, a, base + 1);
        float cg = __shfl_sync(0xffffffffu, a, base + 2);
        float og = __shfl_sync(0xffffffffu, a, base + 3);

        float hn = 0.f;
        if (owner) {
            c_val = c_val * fg + ig * cg;
            float e = __expf(-2.f * c_val);
            hn = og * (__fdividef(2.f, 1.f + e) - 1.f);
        }

        if (not_last) {
            // empty[nb] released by readers at step t-3 -> normally satisfied
            if (t >= 3) mbar_wait(my_mb + 32 + nb * 8, ((unsigned)(t - 3) >> 2) & 1u);
            if (owner) {
                unsigned off4 = (unsigned)(nb * (2 * Hsz) + b_me * Hsz + jg_me) * 4u;
                unsigned hbits = __float_as_uint(hn);
                #pragma unroll
                for (int r = 0; r < 8; r++)
                    asm volatile(
                        "st.async.weak.shared::cluster.mbarrier::complete_tx::bytes.b32 [%0], %1, [%2];"
                        :: "r"(s_rh[r] + off4), "r"(hbits),
                           "r"(s_rmb[r] + (unsigned)nb * 8u) : "memory");
            }
        }

        // gmem output after the broadcast (off the critical chain)
        if (owner) {
            out_hj[(size_t)t * Hsz] = hn;
            if (!not_last && write_finals) {
                out[fin_off + (size_t)bg_me * Hsz + jg_me] = hn;                          // h_f
                out[fin_off + (size_t)Bsz * Hsz + (size_t)bg_me * Hsz + jg_me] = c_val;   // c_f
            }
        }
        xv = xv_next;
    }

    // lifetime safety: no CTA exits while cluster peers may have ops in flight
    asm volatile("barrier.cluster.arrive.aligned;" ::: "memory");
    asm volatile("barrier.cluster.wait.aligned;" ::: "memory");
}

// ------------------------------- launch ----------------------------------------
extern "C" void kernel_launch(void* const* d_in, const int* in_sizes, int n_in,
                              void* d_out, int out_size) {
    const float* x  = (const float*)d_in[0];
    const float* h0 = (const float*)d_in[1];
    const float* c0 = (const float*)d_in[2];
    const float* Wf = (const float*)d_in[3];
    const float* bf = (const float*)d_in[4];
    const float* Wi = (const float*)d_in[5];
    const float* bi = (const float*)d_in[6];
    const float* Wc = (const float*)d_in[7];
    const float* bc = (const float*)d_in[8];
    const float* Wo = (const float*)d_in[9];
    const float* bo = (const float*)d_in[10];
    float* out = (float*)d_out;

    int full = Bsz * Ssz * Hsz + 2 * Bsz * Hsz;
    int write_finals = (out_size >= full) ? 1 : 0;

    pack_kernel<<<512, 256>>>(Wf, Wi, Wc, Wo, bf, bi, bc, bo);

    dim3 grid_x(8, 512);
    xproj_kernel<<<grid_x, 256>>>(x);

    lstm_rec<<<128, 256>>>(h0, c0, out, write_finals);
}